// round 1
// baseline (speedup 1.0000x reference)
#include <cuda_runtime.h>

#define NN 40000
#define EE 640000
#define DIN 256
#define HH 128
#define CC 64

// Scratch (device globals — no allocation allowed in kernel_launch)
__device__ float g_y[NN * HH];   // GEMM output buffer
__device__ float g_h[NN * HH];   // hidden state
__device__ float g_t[NN * HH];   // spmm accumulation buffer

// ---------------------------------------------------------------------------
// Tiled SGEMM with fused bias: Out[M,BN] = A[M,K] @ W[K,BN] + bias[BN]
// BN equals the full output width (128 or 64), so grid is 1-D over row tiles.
// ---------------------------------------------------------------------------
template<int BM, int BN, int BK, int TM, int TN>
__global__ void sgemm_bias(const float* __restrict__ A, const float* __restrict__ W,
                           const float* __restrict__ bias, float* __restrict__ Out,
                           int M, int K) {
    constexpr int TX = BN / TN;       // thread cols
    constexpr int TY = BM / TM;       // thread rows
    constexpr int NT = TX * TY;       // 256 threads

    __shared__ float As[BK][BM + 1];  // +1 pad: conflict-free transpose store
    __shared__ float Ws[BK][BN];

    const int tid = threadIdx.x;
    const int tx = tid % TX;
    const int ty = tid / TX;
    const int row0 = blockIdx.x * BM;

    float acc[TM][TN];
    #pragma unroll
    for (int i = 0; i < TM; i++)
        #pragma unroll
        for (int j = 0; j < TN; j++) acc[i][j] = 0.f;

    for (int k0 = 0; k0 < K; k0 += BK) {
        // Load A tile (BM x BK), store transposed As[k][m]
        for (int i = tid; i < BM * BK / 4; i += NT) {
            int r  = i / (BK / 4);
            int c4 = i % (BK / 4);
            int gr = row0 + r;
            float4 v = make_float4(0.f, 0.f, 0.f, 0.f);
            if (gr < M) v = *(const float4*)(A + (size_t)gr * K + k0 + c4 * 4);
            As[c4 * 4 + 0][r] = v.x;
            As[c4 * 4 + 1][r] = v.y;
            As[c4 * 4 + 2][r] = v.z;
            As[c4 * 4 + 3][r] = v.w;
        }
        // Load W tile (BK x BN), direct layout
        for (int i = tid; i < BK * BN / 4; i += NT) {
            int kk = i / (BN / 4);
            int n4 = i % (BN / 4);
            *(float4*)&Ws[kk][n4 * 4] =
                *(const float4*)(W + (size_t)(k0 + kk) * BN + n4 * 4);
        }
        __syncthreads();

        #pragma unroll
        for (int kk = 0; kk < BK; kk++) {
            float a[TM], b[TN];
            #pragma unroll
            for (int i = 0; i < TM; i++) a[i] = As[kk][ty * TM + i];
            #pragma unroll
            for (int j = 0; j < TN; j++) b[j] = Ws[kk][tx * TN + j];
            #pragma unroll
            for (int i = 0; i < TM; i++)
                #pragma unroll
                for (int j = 0; j < TN; j++)
                    acc[i][j] = fmaf(a[i], b[j], acc[i][j]);
        }
        __syncthreads();
    }

    float bb[TN];
    #pragma unroll
    for (int j = 0; j < TN; j++) bb[j] = bias[tx * TN + j];

    #pragma unroll
    for (int i = 0; i < TM; i++) {
        int gr = row0 + ty * TM + i;
        if (gr < M) {
            #pragma unroll
            for (int j = 0; j < TN; j += 4) {
                float4 v;
                v.x = acc[i][j + 0] + bb[j + 0];
                v.y = acc[i][j + 1] + bb[j + 1];
                v.z = acc[i][j + 2] + bb[j + 2];
                v.w = acc[i][j + 3] + bb[j + 3];
                *(float4*)(Out + (size_t)gr * BN + tx * TN + j) = v;
            }
        }
    }
}

// ---------------------------------------------------------------------------
// Edge-parallel SPMM: out[row[e]] += val[e] * mat[col[e]], one warp per edge.
// Dense operand lives in L2 (20.5 MB << 126 MB); scatter via atomicAdd.
// ---------------------------------------------------------------------------
template<int D>
__global__ void spmm_kernel(const int* __restrict__ row, const int* __restrict__ col,
                            const float* __restrict__ val, const float* __restrict__ mat,
                            float* __restrict__ out, int E) {
    int warp = (blockIdx.x * blockDim.x + threadIdx.x) >> 5;
    int lane = threadIdx.x & 31;
    if (warp >= E) return;
    int r = __ldg(&row[warp]);
    int c = __ldg(&col[warp]);
    float v = __ldg(&val[warp]);
    if (D == 128) {
        float4 m = *(const float4*)(mat + (size_t)c * 128 + lane * 4);
        float* o = out + (size_t)r * 128 + lane * 4;
        atomicAdd(o + 0, v * m.x);
        atomicAdd(o + 1, v * m.y);
        atomicAdd(o + 2, v * m.z);
        atomicAdd(o + 3, v * m.w);
    } else {  // D == 64
        float2 m = *(const float2*)(mat + (size_t)c * 64 + lane * 2);
        float* o = out + (size_t)r * 64 + lane * 2;
        atomicAdd(o + 0, v * m.x);
        atomicAdd(o + 1, v * m.y);
    }
}

// ---------------------------------------------------------------------------
// Elementwise helpers (all float4-vectorized)
// ---------------------------------------------------------------------------
__global__ void zero_kernel(float* __restrict__ p, int n4) {
    int i = blockIdx.x * blockDim.x + threadIdx.x;
    if (i < n4) ((float4*)p)[i] = make_float4(0.f, 0.f, 0.f, 0.f);
}

__global__ void relu_kernel(const float* __restrict__ src, float* __restrict__ dst, int n4) {
    int i = blockIdx.x * blockDim.x + threadIdx.x;
    if (i >= n4) return;
    float4 v = ((const float4*)src)[i];
    v.x = fmaxf(v.x, 0.f);
    v.y = fmaxf(v.y, 0.f);
    v.z = fmaxf(v.z, 0.f);
    v.w = fmaxf(v.w, 0.f);
    ((float4*)dst)[i] = v;
}

__global__ void residual_kernel(float* __restrict__ h, const float* __restrict__ t,
                                const float* __restrict__ ts, int n4) {
    int i = blockIdx.x * blockDim.x + threadIdx.x;
    if (i >= n4) return;
    float dt = *ts;
    float4 hv = ((const float4*)h)[i];
    float4 tv = ((const float4*)t)[i];
    hv.x = fmaf(fmaxf(tv.x, 0.f), dt, hv.x);
    hv.y = fmaf(fmaxf(tv.y, 0.f), dt, hv.y);
    hv.z = fmaf(fmaxf(tv.z, 0.f), dt, hv.z);
    hv.w = fmaf(fmaxf(tv.w, 0.f), dt, hv.w);
    ((float4*)h)[i] = hv;
}

// ---------------------------------------------------------------------------
// Launch sequence
// ---------------------------------------------------------------------------
extern "C" void kernel_launch(void* const* d_in, const int* in_sizes, int n_in,
                              void* d_out, int out_size) {
    const float* x    = (const float*)d_in[0];
    const int*   erow = (const int*)  d_in[1];
    const int*   ecol = (const int*)  d_in[2];
    const float* eval = (const float*)d_in[3];
    const float* w1   = (const float*)d_in[4];
    const float* b1   = (const float*)d_in[5];
    const float* wm   = (const float*)d_in[6];
    const float* bm   = (const float*)d_in[7];
    const float* w2   = (const float*)d_in[8];
    const float* b2   = (const float*)d_in[9];
    const float* ts   = (const float*)d_in[10];
    float* out = (float*)d_out;

    float *y, *h, *t;
    cudaGetSymbolAddress((void**)&y, g_y);
    cudaGetSymbolAddress((void**)&h, g_h);
    cudaGetSymbolAddress((void**)&t, g_t);

    const int gemm_blocks = (NN + 127) / 128;          // 313
    const int spmm_blocks = (EE + 7) / 8;              // 80000 (8 warps/block)
    const int ew4 = NN * HH / 4;                       // 1.28M float4
    const int ew_blocks = (ew4 + 255) / 256;
    const int out4 = NN * CC / 4;
    const int out_blocks = (out4 + 255) / 256;

    // Stage 1: h = relu(A @ (x W1 + b1))
    sgemm_bias<128, 128, 32, 8, 8><<<gemm_blocks, 256>>>(x, w1, b1, y, NN, DIN);
    zero_kernel<<<ew_blocks, 256>>>(t, ew4);
    spmm_kernel<128><<<spmm_blocks, 256>>>(erow, ecol, eval, y, t, EE);
    relu_kernel<<<ew_blocks, 256>>>(t, h, ew4);

    // Stage 2,3: h += relu(A @ (h Wm + bm)) * dt
    for (int i = 0; i < 2; i++) {
        sgemm_bias<128, 128, 32, 8, 8><<<gemm_blocks, 256>>>(
            h, wm + (size_t)i * HH * HH, bm + (size_t)i * HH, y, NN, HH);
        zero_kernel<<<ew_blocks, 256>>>(t, ew4);
        spmm_kernel<128><<<spmm_blocks, 256>>>(erow, ecol, eval, y, t, EE);
        residual_kernel<<<ew_blocks, 256>>>(h, t, ts, ew4);
    }

    // Stage 4: out = A @ (h W2 + b2)
    sgemm_bias<128, 64, 32, 8, 4><<<gemm_blocks, 256>>>(h, w2, b2, y, NN, HH);
    zero_kernel<<<out_blocks, 256>>>(out, out4);
    spmm_kernel<64><<<spmm_blocks, 256>>>(erow, ecol, eval, y, out, EE);
}

// round 2
// speedup vs baseline: 2.1808x; 2.1808x over previous
#include <cuda_runtime.h>

#define NN 40000
#define EE 640000
#define DIN 256
#define HH 128
#define CC 64

// Scratch (device globals — allocation is forbidden in kernel_launch)
__device__ float g_y[NN * HH];      // GEMM output buffer
__device__ float g_h[NN * HH];      // hidden state
__device__ int   g_cnt[NN];         // row degree histogram
__device__ int   g_rowptr[NN + 1];  // CSR row pointers
__device__ int   g_cursor[NN];      // scatter cursors
__device__ int   g_ccol[EE];        // CSR column indices
__device__ float g_cval[EE];        // CSR edge values

// ---------------------------------------------------------------------------
// CSR construction
// ---------------------------------------------------------------------------
__global__ void zero_int(int* __restrict__ p, int n) {
    int i = blockIdx.x * blockDim.x + threadIdx.x;
    if (i < n) p[i] = 0;
}

__global__ void hist_kernel(const int* __restrict__ row, int* __restrict__ cnt, int E) {
    int i = blockIdx.x * blockDim.x + threadIdx.x;
    if (i < E) atomicAdd(&cnt[row[i]], 1);
}

// Single-block scan over NN counts -> rowptr (inclusive at i+1) + cursor (exclusive)
__global__ void scan_kernel(const int* __restrict__ cnt, int* __restrict__ rowptr,
                            int* __restrict__ cursor) {
    __shared__ int wsum[32];
    __shared__ int carry_s;
    const int tid = threadIdx.x;
    const int lane = tid & 31;
    const int wid = tid >> 5;
    if (tid == 0) { carry_s = 0; rowptr[0] = 0; }
    __syncthreads();

    for (int base = 0; base < NN; base += 1024) {
        int i = base + tid;
        int v = (i < NN) ? cnt[i] : 0;
        int incl = v;
        #pragma unroll
        for (int o = 1; o < 32; o <<= 1) {
            int t = __shfl_up_sync(0xFFFFFFFFu, incl, o);
            if (lane >= o) incl += t;
        }
        if (lane == 31) wsum[wid] = incl;
        __syncthreads();
        if (wid == 0) {
            int w = wsum[lane];
            #pragma unroll
            for (int o = 1; o < 32; o <<= 1) {
                int t = __shfl_up_sync(0xFFFFFFFFu, w, o);
                if (lane >= o) w += t;
            }
            wsum[lane] = w;
        }
        __syncthreads();
        int offset = (wid > 0) ? wsum[wid - 1] : 0;
        int total = wsum[31];
        int carry = carry_s;
        incl += offset;
        if (i < NN) {
            rowptr[i + 1] = carry + incl;
            cursor[i]     = carry + incl - v;
        }
        __syncthreads();
        if (tid == 0) carry_s = carry + total;
        __syncthreads();
    }
}

__global__ void scatter_kernel(const int* __restrict__ row, const int* __restrict__ col,
                               const float* __restrict__ val, int* __restrict__ cursor,
                               int* __restrict__ ccol, float* __restrict__ cval, int E) {
    int i = blockIdx.x * blockDim.x + threadIdx.x;
    if (i >= E) return;
    int pos = atomicAdd(&cursor[row[i]], 1);
    ccol[pos] = col[i];
    cval[pos] = val[i];
}

// ---------------------------------------------------------------------------
// CSR SPMM (gather, one warp per row) with fused epilogue.
// MODE 0: dst = relu(acc)       (stage 1)
// MODE 1: dst += relu(acc)*dt   (residual stages)
// MODE 2: dst = acc             (output stage)
// ---------------------------------------------------------------------------
template<int D, int MODE>
__global__ void spmm_csr(const int* __restrict__ rowptr, const int* __restrict__ ccol,
                         const float* __restrict__ cval, const float* __restrict__ mat,
                         float* __restrict__ dst, const float* __restrict__ ts) {
    int r = blockIdx.x * (blockDim.x >> 5) + (threadIdx.x >> 5);
    if (r >= NN) return;
    int lane = threadIdx.x & 31;
    int s = __ldg(&rowptr[r]);
    int e = __ldg(&rowptr[r + 1]);

    if (D == 128) {
        float4 acc = make_float4(0.f, 0.f, 0.f, 0.f);
        for (int i = s; i < e; i++) {
            int   c = __ldg(&ccol[i]);
            float v = __ldg(&cval[i]);
            float4 m = __ldg((const float4*)(mat + (size_t)c * 128) + lane);
            acc.x = fmaf(v, m.x, acc.x);
            acc.y = fmaf(v, m.y, acc.y);
            acc.z = fmaf(v, m.z, acc.z);
            acc.w = fmaf(v, m.w, acc.w);
        }
        float4* o = (float4*)(dst + (size_t)r * 128) + lane;
        if (MODE == 0) {
            acc.x = fmaxf(acc.x, 0.f); acc.y = fmaxf(acc.y, 0.f);
            acc.z = fmaxf(acc.z, 0.f); acc.w = fmaxf(acc.w, 0.f);
            *o = acc;
        } else if (MODE == 1) {
            float dt = *ts;
            float4 h = *o;
            h.x = fmaf(fmaxf(acc.x, 0.f), dt, h.x);
            h.y = fmaf(fmaxf(acc.y, 0.f), dt, h.y);
            h.z = fmaf(fmaxf(acc.z, 0.f), dt, h.z);
            h.w = fmaf(fmaxf(acc.w, 0.f), dt, h.w);
            *o = h;
        } else {
            *o = acc;
        }
    } else {  // D == 64
        float2 acc = make_float2(0.f, 0.f);
        for (int i = s; i < e; i++) {
            int   c = __ldg(&ccol[i]);
            float v = __ldg(&cval[i]);
            float2 m = __ldg((const float2*)(mat + (size_t)c * 64) + lane);
            acc.x = fmaf(v, m.x, acc.x);
            acc.y = fmaf(v, m.y, acc.y);
        }
        float2* o = (float2*)(dst + (size_t)r * 64) + lane;
        *o = acc;  // only MODE 2 used at D=64
    }
}

// ---------------------------------------------------------------------------
// Tiled SGEMM with fused bias: Out[M,BN] = A[M,K] @ W[K,BN] + bias[BN]
// ---------------------------------------------------------------------------
template<int BM, int BN, int BK, int TM, int TN>
__global__ void sgemm_bias(const float* __restrict__ A, const float* __restrict__ W,
                           const float* __restrict__ bias, float* __restrict__ Out,
                           int M, int K) {
    constexpr int TX = BN / TN;
    constexpr int TY = BM / TM;
    constexpr int NT = TX * TY;

    __shared__ float As[BK][BM + 1];
    __shared__ float Ws[BK][BN];

    const int tid = threadIdx.x;
    const int tx = tid % TX;
    const int ty = tid / TX;
    const int row0 = blockIdx.x * BM;

    float acc[TM][TN];
    #pragma unroll
    for (int i = 0; i < TM; i++)
        #pragma unroll
        for (int j = 0; j < TN; j++) acc[i][j] = 0.f;

    for (int k0 = 0; k0 < K; k0 += BK) {
        for (int i = tid; i < BM * BK / 4; i += NT) {
            int r  = i / (BK / 4);
            int c4 = i % (BK / 4);
            int gr = row0 + r;
            float4 v = make_float4(0.f, 0.f, 0.f, 0.f);
            if (gr < M) v = *(const float4*)(A + (size_t)gr * K + k0 + c4 * 4);
            As[c4 * 4 + 0][r] = v.x;
            As[c4 * 4 + 1][r] = v.y;
            As[c4 * 4 + 2][r] = v.z;
            As[c4 * 4 + 3][r] = v.w;
        }
        for (int i = tid; i < BK * BN / 4; i += NT) {
            int kk = i / (BN / 4);
            int n4 = i % (BN / 4);
            *(float4*)&Ws[kk][n4 * 4] =
                *(const float4*)(W + (size_t)(k0 + kk) * BN + n4 * 4);
        }
        __syncthreads();

        #pragma unroll
        for (int kk = 0; kk < BK; kk++) {
            float a[TM], b[TN];
            #pragma unroll
            for (int i = 0; i < TM; i++) a[i] = As[kk][ty * TM + i];
            #pragma unroll
            for (int j = 0; j < TN; j++) b[j] = Ws[kk][tx * TN + j];
            #pragma unroll
            for (int i = 0; i < TM; i++)
                #pragma unroll
                for (int j = 0; j < TN; j++)
                    acc[i][j] = fmaf(a[i], b[j], acc[i][j]);
        }
        __syncthreads();
    }

    float bb[TN];
    #pragma unroll
    for (int j = 0; j < TN; j++) bb[j] = bias[tx * TN + j];

    #pragma unroll
    for (int i = 0; i < TM; i++) {
        int gr = row0 + ty * TM + i;
        if (gr < M) {
            #pragma unroll
            for (int j = 0; j < TN; j += 4) {
                float4 v;
                v.x = acc[i][j + 0] + bb[j + 0];
                v.y = acc[i][j + 1] + bb[j + 1];
                v.z = acc[i][j + 2] + bb[j + 2];
                v.w = acc[i][j + 3] + bb[j + 3];
                *(float4*)(Out + (size_t)gr * BN + tx * TN + j) = v;
            }
        }
    }
}

// ---------------------------------------------------------------------------
// Launch sequence
// ---------------------------------------------------------------------------
extern "C" void kernel_launch(void* const* d_in, const int* in_sizes, int n_in,
                              void* d_out, int out_size) {
    const float* x    = (const float*)d_in[0];
    const int*   erow = (const int*)  d_in[1];
    const int*   ecol = (const int*)  d_in[2];
    const float* eval = (const float*)d_in[3];
    const float* w1   = (const float*)d_in[4];
    const float* b1   = (const float*)d_in[5];
    const float* wm   = (const float*)d_in[6];
    const float* bm   = (const float*)d_in[7];
    const float* w2   = (const float*)d_in[8];
    const float* b2   = (const float*)d_in[9];
    const float* ts   = (const float*)d_in[10];
    float* out = (float*)d_out;

    float *y, *h, *cval;
    int *cnt, *rowptr, *cursor, *ccol;
    cudaGetSymbolAddress((void**)&y,      g_y);
    cudaGetSymbolAddress((void**)&h,      g_h);
    cudaGetSymbolAddress((void**)&cnt,    g_cnt);
    cudaGetSymbolAddress((void**)&rowptr, g_rowptr);
    cudaGetSymbolAddress((void**)&cursor, g_cursor);
    cudaGetSymbolAddress((void**)&ccol,   g_ccol);
    cudaGetSymbolAddress((void**)&cval,   g_cval);

    const int gemm_blocks = (NN + 127) / 128;
    const int spmm_blocks = (NN + 7) / 8;            // 1 warp/row, 8 rows/block
    const int e_blocks = (EE + 255) / 256;

    // Build CSR
    zero_int<<<(NN + 255) / 256, 256>>>(cnt, NN);
    hist_kernel<<<e_blocks, 256>>>(erow, cnt, EE);
    scan_kernel<<<1, 1024>>>(cnt, rowptr, cursor);
    scatter_kernel<<<e_blocks, 256>>>(erow, ecol, eval, cursor, ccol, cval, EE);

    // Stage 1: h = relu(A @ (x W1 + b1))
    sgemm_bias<128, 128, 32, 8, 8><<<gemm_blocks, 256>>>(x, w1, b1, y, NN, DIN);
    spmm_csr<128, 0><<<spmm_blocks, 256>>>(rowptr, ccol, cval, y, h, ts);

    // Stage 2,3: h += relu(A @ (h Wm + bm)) * dt
    for (int i = 0; i < 2; i++) {
        sgemm_bias<128, 128, 32, 8, 8><<<gemm_blocks, 256>>>(
            h, wm + (size_t)i * HH * HH, bm + (size_t)i * HH, y, NN, HH);
        spmm_csr<128, 1><<<spmm_blocks, 256>>>(rowptr, ccol, cval, y, h, ts);
    }

    // Stage 4: out = A @ (h W2 + b2)
    sgemm_bias<128, 64, 32, 8, 4><<<gemm_blocks, 256>>>(h, w2, b2, y, NN, HH);
    spmm_csr<64, 2><<<spmm_blocks, 256>>>(rowptr, ccol, cval, y, out, ts);
}

// round 4
// speedup vs baseline: 3.2382x; 1.4849x over previous
#include <cuda_runtime.h>
#include <cuda_bf16.h>
#include <cstdint>

#define NN 40000
#define EE 640000
#define DIN 256
#define HH 128
#define CC 64

// ---------------------------------------------------------------------------
// Scratch (device globals — allocation forbidden in kernel_launch)
// ---------------------------------------------------------------------------
__device__ float g_y[NN * HH];                 // GEMM output buffer
__device__ float g_h[NN * HH];                 // hidden state
__device__ __nv_bfloat16 g_acat[NN * 3 * DIN]; // A_cat [M, 3K] (max K=256)
__device__ __nv_bfloat16 g_w1c[HH * 3 * DIN];  // B_cat^T [N,3K] stage 1
__device__ __nv_bfloat16 g_wmc[2 * HH * 3 * HH];
__device__ __nv_bfloat16 g_w2c[CC * 3 * HH];
__device__ int   g_cnt[NN];
__device__ int   g_rowptr[NN + 1];
__device__ int   g_cursor[NN];
__device__ int   g_ccol[EE];
__device__ float g_cval[EE];

__device__ __forceinline__ uint32_t smem_u32(const void* p) {
    uint32_t a;
    asm("{ .reg .u64 t; cvta.to.shared.u64 t, %1; cvt.u32.u64 %0, t; }" : "=r"(a) : "l"(p));
    return a;
}

// ---------------------------------------------------------------------------
// bf16 GEMM via mma.sync.m16n8k16 (sm_80+ path; no tcgen05 — harness PTX
// target is sm_103 without the 'a' feature set).
//   Out[M,N_] = A_cat[M,KTOT] @ B_cat[KTOT,N_] + bias,  B given as [N_,KTOT].
// CTA: 256 thr (8 warps), tile BM=128 x N_ (full width), BK=64.
// Warp grid 4x2: warp tile 32(m) x N_/2(n). fp32 accumulation.
// smem: 128B rows, swizzle col16 ^= (row&7)  -> conflict-free ldmatrix.
// ---------------------------------------------------------------------------
template<int N_, int KTOT>
__global__ __launch_bounds__(256)
void gemm_mma(const __nv_bfloat16* __restrict__ A,
              const __nv_bfloat16* __restrict__ BT,
              const float* __restrict__ bias,
              float* __restrict__ Out, int M) {
    constexpr int NF = N_ / 16;            // n-frags (8 cols each) per warp
    __shared__ uint8_t sA[128 * 128];      // 128 rows x 64 bf16 (128B)
    __shared__ uint8_t sB[N_ * 128];

    const int tid = threadIdx.x;
    const int wid = tid >> 5;
    const int lane = tid & 31;
    const int wm = wid >> 1;               // 0..3, 32 rows each
    const int wn = wid & 1;                // 0..1, N_/2 cols each
    const int m0 = blockIdx.x * 128;

    const uint32_t sAu = smem_u32(sA);
    const uint32_t sBu = smem_u32(sB);

    float acc[2][NF][4];
    #pragma unroll
    for (int i = 0; i < 2; i++)
        #pragma unroll
        for (int j = 0; j < NF; j++)
            #pragma unroll
            for (int q = 0; q < 4; q++) acc[i][j][q] = 0.f;

    for (int k0 = 0; k0 < KTOT; k0 += 64) {
        // Stage A tile: 128 rows x 128B = 1024 16B chunks
        #pragma unroll
        for (int id = tid; id < 1024; id += 256) {
            int r = id >> 3, c = id & 7;
            uint4 v = make_uint4(0u, 0u, 0u, 0u);
            if (m0 + r < M)
                v = *(const uint4*)(A + (size_t)(m0 + r) * KTOT + k0 + c * 8);
            *(uint4*)(sA + r * 128 + ((c ^ (r & 7)) << 4)) = v;
        }
        // Stage B tile: N_ rows x 128B
        #pragma unroll
        for (int id = tid; id < N_ * 8; id += 256) {
            int r = id >> 3, c = id & 7;
            uint4 v = *(const uint4*)(BT + (size_t)r * KTOT + k0 + c * 8);
            *(uint4*)(sB + r * 128 + ((c ^ (r & 7)) << 4)) = v;
        }
        __syncthreads();

        #pragma unroll
        for (int ks = 0; ks < 4; ks++) {
            const int kk = ks * 16;
            // A fragments: 2 m-frags of 16 rows
            uint32_t a[2][4];
            #pragma unroll
            for (int mf = 0; mf < 2; mf++) {
                int r = wm * 32 + mf * 16 + (lane & 15);
                int kz = kk + (lane >> 4) * 8;
                uint32_t ad = sAu + r * 128 + ((((kz >> 3) ^ (r & 7))) << 4);
                asm volatile("ldmatrix.sync.aligned.m8n8.x4.shared.b16 {%0,%1,%2,%3}, [%4];"
                    : "=r"(a[mf][0]), "=r"(a[mf][1]), "=r"(a[mf][2]), "=r"(a[mf][3])
                    : "r"(ad));
            }
            // B fragments: NF n-frags, loaded 2 at a time via x4
            uint32_t b[NF][2];
            #pragma unroll
            for (int nf2 = 0; nf2 < NF / 2; nf2++) {
                int n0 = wn * (NF * 8) + nf2 * 16;
                int r = n0 + (lane & 7) + ((lane >> 4) << 3);
                int kz = kk + ((lane >> 3) & 1) * 8;
                uint32_t ad = sBu + r * 128 + ((((kz >> 3) ^ (r & 7))) << 4);
                asm volatile("ldmatrix.sync.aligned.m8n8.x4.shared.b16 {%0,%1,%2,%3}, [%4];"
                    : "=r"(b[2 * nf2][0]), "=r"(b[2 * nf2][1]),
                      "=r"(b[2 * nf2 + 1][0]), "=r"(b[2 * nf2 + 1][1])
                    : "r"(ad));
            }
            #pragma unroll
            for (int mf = 0; mf < 2; mf++)
                #pragma unroll
                for (int nf = 0; nf < NF; nf++) {
                    asm volatile(
                        "mma.sync.aligned.m16n8k16.row.col.f32.bf16.bf16.f32 "
                        "{%0,%1,%2,%3}, {%4,%5,%6,%7}, {%8,%9}, {%0,%1,%2,%3};"
                        : "+f"(acc[mf][nf][0]), "+f"(acc[mf][nf][1]),
                          "+f"(acc[mf][nf][2]), "+f"(acc[mf][nf][3])
                        : "r"(a[mf][0]), "r"(a[mf][1]), "r"(a[mf][2]), "r"(a[mf][3]),
                          "r"(b[nf][0]), "r"(b[nf][1]));
                }
        }
        __syncthreads();
    }

    // Epilogue: d0,d1 -> (row lane/4, cols 2*(lane%4)); d2,d3 -> row +8
    #pragma unroll
    for (int mf = 0; mf < 2; mf++) {
        int r1 = m0 + wm * 32 + mf * 16 + (lane >> 2);
        int r2 = r1 + 8;
        #pragma unroll
        for (int nf = 0; nf < NF; nf++) {
            int col = wn * (NF * 8) + nf * 8 + (lane & 3) * 2;
            float bx = __ldg(bias + col), by = __ldg(bias + col + 1);
            if (r1 < M) {
                float2 v = make_float2(acc[mf][nf][0] + bx, acc[mf][nf][1] + by);
                *(float2*)(Out + (size_t)r1 * N_ + col) = v;
            }
            if (r2 < M) {
                float2 v = make_float2(acc[mf][nf][2] + bx, acc[mf][nf][3] + by);
                *(float2*)(Out + (size_t)r2 * N_ + col) = v;
            }
        }
    }
}

// ---------------------------------------------------------------------------
// Split kernels: A_cat = [hi | lo | hi], B_cat^T = [hi | hi | lo]
// ---------------------------------------------------------------------------
__device__ __forceinline__ __nv_bfloat162 bhi2(float x, float y) {
    __nv_bfloat162 p;
    p.x = __float2bfloat16(x);
    p.y = __float2bfloat16(y);
    return p;
}
__device__ __forceinline__ __nv_bfloat162 blo2(float x, float y, __nv_bfloat162 h) {
    __nv_bfloat162 p;
    p.x = __float2bfloat16(x - __bfloat162float(h.x));
    p.y = __float2bfloat16(y - __bfloat162float(h.y));
    return p;
}

// x [M,K] float -> acat [M,3K] = [hi,lo,hi]
template<int K>
__global__ void asplit3(const float* __restrict__ src, __nv_bfloat16* __restrict__ acat, int n4) {
    int i = blockIdx.x * blockDim.x + threadIdx.x;
    if (i >= n4) return;
    int r = i / (K / 4), c = i % (K / 4);
    float4 v = ((const float4*)src)[i];
    __nv_bfloat162 h0 = bhi2(v.x, v.y), h1 = bhi2(v.z, v.w);
    __nv_bfloat162 l0 = blo2(v.x, v.y, h0), l1 = blo2(v.z, v.w, h1);
    __nv_bfloat162* row = (__nv_bfloat162*)(acat + (size_t)r * 3 * K);
    row[2 * c]              = h0;
    row[2 * c + 1]          = h1;
    row[K / 2 + 2 * c]      = l0;
    row[K / 2 + 2 * c + 1]  = l1;
    row[K + 2 * c]          = h0;
    row[K + 2 * c + 1]      = h1;
}

// W [K,N] -> BT_cat [N,3K] = [hi,hi,lo]
__global__ void wsplit3(const float* __restrict__ w, __nv_bfloat16* __restrict__ bt,
                        int K, int N) {
    int i = blockIdx.x * blockDim.x + threadIdx.x;
    if (i >= K * N) return;
    int k = i / N, n = i % N;
    float f = w[i];
    __nv_bfloat16 h = __float2bfloat16(f);
    __nv_bfloat16 l = __float2bfloat16(f - __bfloat162float(h));
    __nv_bfloat16* row = bt + (size_t)n * 3 * K;
    row[k] = h;
    row[K + k] = h;
    row[2 * K + k] = l;
}

// ---------------------------------------------------------------------------
// CSR construction
// ---------------------------------------------------------------------------
__global__ void zero_int(int* __restrict__ p, int n) {
    int i = blockIdx.x * blockDim.x + threadIdx.x;
    if (i < n) p[i] = 0;
}
__global__ void hist_kernel(const int* __restrict__ row, int* __restrict__ cnt, int E) {
    int i = blockIdx.x * blockDim.x + threadIdx.x;
    if (i < E) atomicAdd(&cnt[row[i]], 1);
}
__global__ void scan_kernel(const int* __restrict__ cnt, int* __restrict__ rowptr,
                            int* __restrict__ cursor) {
    __shared__ int wsum[32];
    __shared__ int carry_s;
    const int tid = threadIdx.x;
    const int lane = tid & 31;
    const int wid = tid >> 5;
    if (tid == 0) { carry_s = 0; rowptr[0] = 0; }
    __syncthreads();
    for (int base = 0; base < NN; base += 1024) {
        int i = base + tid;
        int v = (i < NN) ? cnt[i] : 0;
        int incl = v;
        #pragma unroll
        for (int o = 1; o < 32; o <<= 1) {
            int t = __shfl_up_sync(0xFFFFFFFFu, incl, o);
            if (lane >= o) incl += t;
        }
        if (lane == 31) wsum[wid] = incl;
        __syncthreads();
        if (wid == 0) {
            int w = wsum[lane];
            #pragma unroll
            for (int o = 1; o < 32; o <<= 1) {
                int t = __shfl_up_sync(0xFFFFFFFFu, w, o);
                if (lane >= o) w += t;
            }
            wsum[lane] = w;
        }
        __syncthreads();
        int offset = (wid > 0) ? wsum[wid - 1] : 0;
        int total = wsum[31];
        int carry = carry_s;
        incl += offset;
        if (i < NN) {
            rowptr[i + 1] = carry + incl;
            cursor[i]     = carry + incl - v;
        }
        __syncthreads();
        if (tid == 0) carry_s = carry + total;
        __syncthreads();
    }
}
__global__ void scatter_kernel(const int* __restrict__ row, const int* __restrict__ col,
                               const float* __restrict__ val, int* __restrict__ cursor,
                               int* __restrict__ ccol, float* __restrict__ cval, int E) {
    int i = blockIdx.x * blockDim.x + threadIdx.x;
    if (i >= E) return;
    int pos = atomicAdd(&cursor[row[i]], 1);
    ccol[pos] = col[i];
    cval[pos] = val[i];
}

// ---------------------------------------------------------------------------
// CSR SPMM (1 warp/row) with fused epilogue + fused bf16x3 split output.
// MODE 0: h = relu(acc);      split(h) -> acat[.,384]
// MODE 1: h += relu(acc)*dt;  split(h) -> acat[.,384]
// MODE 2: dst = acc   (D=64, no split)
// ---------------------------------------------------------------------------
template<int D, int MODE>
__global__ void spmm_csr(const int* __restrict__ rowptr, const int* __restrict__ ccol,
                         const float* __restrict__ cval, const float* __restrict__ mat,
                         float* __restrict__ dst, const float* __restrict__ ts,
                         __nv_bfloat16* __restrict__ acat) {
    int r = blockIdx.x * (blockDim.x >> 5) + (threadIdx.x >> 5);
    if (r >= NN) return;
    int lane = threadIdx.x & 31;
    int s = __ldg(&rowptr[r]);
    int e = __ldg(&rowptr[r + 1]);

    if (D == 128) {
        float4 acc = make_float4(0.f, 0.f, 0.f, 0.f);
        for (int i = s; i < e; i++) {
            int   c = __ldg(&ccol[i]);
            float v = __ldg(&cval[i]);
            float4 m = __ldg((const float4*)(mat + (size_t)c * 128) + lane);
            acc.x = fmaf(v, m.x, acc.x);
            acc.y = fmaf(v, m.y, acc.y);
            acc.z = fmaf(v, m.z, acc.z);
            acc.w = fmaf(v, m.w, acc.w);
        }
        float4* o = (float4*)(dst + (size_t)r * 128) + lane;
        float4 hv;
        if (MODE == 0) {
            hv.x = fmaxf(acc.x, 0.f); hv.y = fmaxf(acc.y, 0.f);
            hv.z = fmaxf(acc.z, 0.f); hv.w = fmaxf(acc.w, 0.f);
        } else {
            float dt = *ts;
            hv = *o;
            hv.x = fmaf(fmaxf(acc.x, 0.f), dt, hv.x);
            hv.y = fmaf(fmaxf(acc.y, 0.f), dt, hv.y);
            hv.z = fmaf(fmaxf(acc.z, 0.f), dt, hv.z);
            hv.w = fmaf(fmaxf(acc.w, 0.f), dt, hv.w);
        }
        *o = hv;
        // fused split: acat row = [hi(128) | lo(128) | hi(128)]
        __nv_bfloat162 h0 = bhi2(hv.x, hv.y), h1 = bhi2(hv.z, hv.w);
        __nv_bfloat162 l0 = blo2(hv.x, hv.y, h0), l1 = blo2(hv.z, hv.w, h1);
        __nv_bfloat162* row = (__nv_bfloat162*)(acat + (size_t)r * 384);
        row[2 * lane]          = h0;
        row[2 * lane + 1]      = h1;
        row[64 + 2 * lane]     = l0;
        row[64 + 2 * lane + 1] = l1;
        row[128 + 2 * lane]    = h0;
        row[128 + 2 * lane + 1] = h1;
    } else {
        float2 acc = make_float2(0.f, 0.f);
        for (int i = s; i < e; i++) {
            int   c = __ldg(&ccol[i]);
            float v = __ldg(&cval[i]);
            float2 m = __ldg((const float2*)(mat + (size_t)c * 64) + lane);
            acc.x = fmaf(v, m.x, acc.x);
            acc.y = fmaf(v, m.y, acc.y);
        }
        *((float2*)(dst + (size_t)r * 64) + lane) = acc;
    }
}

// ---------------------------------------------------------------------------
// Launch sequence
// ---------------------------------------------------------------------------
extern "C" void kernel_launch(void* const* d_in, const int* in_sizes, int n_in,
                              void* d_out, int out_size) {
    const float* x    = (const float*)d_in[0];
    const int*   erow = (const int*)  d_in[1];
    const int*   ecol = (const int*)  d_in[2];
    const float* eval = (const float*)d_in[3];
    const float* w1   = (const float*)d_in[4];
    const float* b1   = (const float*)d_in[5];
    const float* wm   = (const float*)d_in[6];
    const float* bm   = (const float*)d_in[7];
    const float* w2   = (const float*)d_in[8];
    const float* b2   = (const float*)d_in[9];
    const float* ts   = (const float*)d_in[10];
    float* out = (float*)d_out;

    float *y, *h, *cval;
    int *cnt, *rowptr, *cursor, *ccol;
    __nv_bfloat16 *acat, *w1c, *wmc, *w2c;
    cudaGetSymbolAddress((void**)&y,      g_y);
    cudaGetSymbolAddress((void**)&h,      g_h);
    cudaGetSymbolAddress((void**)&cnt,    g_cnt);
    cudaGetSymbolAddress((void**)&rowptr, g_rowptr);
    cudaGetSymbolAddress((void**)&cursor, g_cursor);
    cudaGetSymbolAddress((void**)&ccol,   g_ccol);
    cudaGetSymbolAddress((void**)&cval,   g_cval);
    cudaGetSymbolAddress((void**)&acat,   g_acat);
    cudaGetSymbolAddress((void**)&w1c,    g_w1c);
    cudaGetSymbolAddress((void**)&wmc,    g_wmc);
    cudaGetSymbolAddress((void**)&w2c,    g_w2c);

    const int gemm_blocks = (NN + 127) / 128;   // 313
    const int spmm_blocks = (NN + 7) / 8;
    const int e_blocks = (EE + 255) / 256;

    // Build CSR
    zero_int<<<(NN + 255) / 256, 256>>>(cnt, NN);
    hist_kernel<<<e_blocks, 256>>>(erow, cnt, EE);
    scan_kernel<<<1, 1024>>>(cnt, rowptr, cursor);
    scatter_kernel<<<e_blocks, 256>>>(erow, ecol, eval, cursor, ccol, cval, EE);

    // Split weights into concatenated bf16 operands
    wsplit3<<<(DIN * HH + 255) / 256, 256>>>(w1, w1c, DIN, HH);
    wsplit3<<<(HH * HH + 255) / 256, 256>>>(wm,           wmc,                        HH, HH);
    wsplit3<<<(HH * HH + 255) / 256, 256>>>(wm + HH * HH, wmc + (size_t)HH * 3 * HH,  HH, HH);
    wsplit3<<<(HH * CC + 255) / 256, 256>>>(w2, w2c, HH, CC);

    // Stage 1: h = relu(A @ (x W1 + b1))
    asplit3<DIN><<<(NN * DIN / 4 + 255) / 256, 256>>>(x, acat, NN * DIN / 4);
    gemm_mma<128, 3 * DIN><<<gemm_blocks, 256>>>(acat, w1c, b1, y, NN);
    spmm_csr<128, 0><<<spmm_blocks, 256>>>(rowptr, ccol, cval, y, h, ts, acat);

    // Stage 2,3: h += relu(A @ (h Wm + bm)) * dt   (split fused into spmm)
    for (int i = 0; i < 2; i++) {
        gemm_mma<128, 3 * HH><<<gemm_blocks, 256>>>(
            acat, wmc + (size_t)i * HH * 3 * HH, bm + (size_t)i * HH, y, NN);
        spmm_csr<128, 1><<<spmm_blocks, 256>>>(rowptr, ccol, cval, y, h, ts, acat);
    }

    // Stage 4: out = A @ (h W2 + b2)
    gemm_mma<64, 3 * HH><<<gemm_blocks, 256>>>(acat, w2c, b2, y, NN);
    spmm_csr<64, 2><<<spmm_blocks, 256>>>(rowptr, ccol, cval, y, out, ts, nullptr);
}

// round 5
// speedup vs baseline: 3.6422x; 1.1248x over previous
#include <cuda_runtime.h>
#include <cuda_bf16.h>
#include <cstdint>

#define NN 40000
#define EE 640000
#define DIN 256
#define HH 128
#define CC 64

// ---------------------------------------------------------------------------
// Scratch (device globals — allocation forbidden in kernel_launch)
// g_acat padded by 128 rows so cp.async row staging never reads OOB.
// ---------------------------------------------------------------------------
__device__ float g_y[NN * HH];                        // GEMM output buffer
__device__ float g_h[NN * HH];                        // hidden state
__device__ __nv_bfloat16 g_acat[(NN + 128) * 2 * DIN]; // A [M, 2K] = [hi|lo]
__device__ __nv_bfloat16 g_w1c[HH * 2 * DIN];          // B^T [N,2K] stage 1
__device__ __nv_bfloat16 g_wmc[2 * HH * 2 * HH];
__device__ __nv_bfloat16 g_w2c[CC * 2 * HH];
__device__ int  g_cnt[NN];
__device__ int  g_rowptr[NN + 1];
__device__ int  g_cursor[NN];
__device__ int2 g_cpack[EE];                           // packed (col, val)

__device__ __forceinline__ uint32_t smem_u32(const void* p) {
    uint32_t a;
    asm("{ .reg .u64 t; cvta.to.shared.u64 t, %1; cvt.u32.u64 %0, t; }" : "=r"(a) : "l"(p));
    return a;
}
__device__ __forceinline__ void cp16(uint32_t dst, const void* src) {
    asm volatile("cp.async.cg.shared.global [%0], [%1], 16;" :: "r"(dst), "l"(src));
}
#define CP_COMMIT() asm volatile("cp.async.commit_group;" ::: "memory")
#define CP_WAIT1()  asm volatile("cp.async.wait_group 1;" ::: "memory")

// ---------------------------------------------------------------------------
// bf16x3 GEMM via mma.sync.m16n8k16 (sm_80+ PTX; tcgen05 unavailable on the
// harness's sm_103 base target).
//   Out[M,N_] = A[M,K]@W[K,N_] + bias computed as hi*hi + lo*hi + hi*lo.
// A2 [M,2K]=[hi|lo] streamed (cp.async, double-buffered); BT2 [N_,2K]=[hi|lo]
// resident in smem for the whole CTA. 256 thr, BM=128, warp grid 4x2.
// ---------------------------------------------------------------------------
template<int N_, int K>
__global__ __launch_bounds__(256)
void gemm_mma(const __nv_bfloat16* __restrict__ A2,
              const __nv_bfloat16* __restrict__ BT2,
              const float* __restrict__ bias,
              float* __restrict__ Out, int M) {
    constexpr int NF = N_ / 16;         // n-frags per warp (wn halves N_)
    constexpr int NITER = K / 64;
    constexpr int BROW = 4 * K;         // B smem row bytes (2K bf16)
    constexpr int ABUF = 128 * 128;     // one A matrix tile (128 rows x 128B)

    extern __shared__ uint8_t smem[];
    uint8_t* sB = smem;                       // N_ * BROW
    uint8_t* sA = smem + N_ * BROW;           // 4 tiles: [buf][hi/lo]
    const uint32_t sBu = smem_u32(sB);
    const uint32_t sAu = smem_u32(sA);

    const int tid = threadIdx.x;
    const int wid = tid >> 5;
    const int lane = tid & 31;
    const int wm = wid >> 1;
    const int wn = wid & 1;
    const int m0 = blockIdx.x * 128;

    float acc[2][NF][4];
    #pragma unroll
    for (int i = 0; i < 2; i++)
        #pragma unroll
        for (int j = 0; j < NF; j++)
            #pragma unroll
            for (int q = 0; q < 4; q++) acc[i][j][q] = 0.f;

    // Resident B load (once)
    for (int idx = tid; idx < N_ * (2 * K) / 8; idx += 256) {
        int r = idx / ((2 * K) / 8);
        int kz = (idx % ((2 * K) / 8)) * 8;
        uint32_t dst = sBu + r * BROW + ((kz >> 6) << 7) + ((((kz >> 3) & 7) ^ (r & 7)) << 4);
        cp16(dst, BT2 + (size_t)r * 2 * K + kz);
    }
    // A stage 0
    auto stageA = [&](int it, int buf) {
        #pragma unroll
        for (int s = 0; s < 8; s++) {
            int idx = s * 256 + tid;
            int hilo = idx >> 10;
            int rem = idx & 1023;
            int r = rem >> 3, c = rem & 7;
            uint32_t dst = sAu + (uint32_t)(buf * 2 + hilo) * ABUF + r * 128 + ((c ^ (r & 7)) << 4);
            cp16(dst, A2 + (size_t)(m0 + r) * 2 * K + hilo * K + it * 64 + c * 8);
        }
    };
    stageA(0, 0);
    CP_COMMIT();

    for (int it = 0; it < NITER; it++) {
        const int buf = it & 1;
        if (it + 1 < NITER) stageA(it + 1, buf ^ 1);
        CP_COMMIT();
        CP_WAIT1();
        __syncthreads();

        const uint32_t aHi = sAu + (uint32_t)(buf * 2) * ABUF;
        const uint32_t aLo = aHi + ABUF;
        #pragma unroll
        for (int ks = 0; ks < 4; ks++) {
            const int kk = ks * 16;
            uint32_t ah[2][4], al[2][4];
            #pragma unroll
            for (int mf = 0; mf < 2; mf++) {
                int r = wm * 32 + mf * 16 + (lane & 15);
                int kz = kk + (lane >> 4) * 8;
                uint32_t off = r * 128 + ((((kz >> 3) ^ (r & 7)) & 7) << 4);
                asm volatile("ldmatrix.sync.aligned.m8n8.x4.shared.b16 {%0,%1,%2,%3}, [%4];"
                    : "=r"(ah[mf][0]), "=r"(ah[mf][1]), "=r"(ah[mf][2]), "=r"(ah[mf][3])
                    : "r"(aHi + off));
                asm volatile("ldmatrix.sync.aligned.m8n8.x4.shared.b16 {%0,%1,%2,%3}, [%4];"
                    : "=r"(al[mf][0]), "=r"(al[mf][1]), "=r"(al[mf][2]), "=r"(al[mf][3])
                    : "r"(aLo + off));
            }
            uint32_t bh[NF][2], bl[NF][2];
            #pragma unroll
            for (int nf2 = 0; nf2 < NF / 2; nf2++) {
                int r = wn * (NF * 8) + nf2 * 16 + (lane & 7) + ((lane >> 4) << 3);
                int kzh = it * 64 + kk + ((lane >> 3) & 1) * 8;
                int kzl = kzh + K;
                uint32_t adh = sBu + r * BROW + ((kzh >> 6) << 7) + ((((kzh >> 3) & 7) ^ (r & 7)) << 4);
                uint32_t adl = sBu + r * BROW + ((kzl >> 6) << 7) + ((((kzl >> 3) & 7) ^ (r & 7)) << 4);
                asm volatile("ldmatrix.sync.aligned.m8n8.x4.shared.b16 {%0,%1,%2,%3}, [%4];"
                    : "=r"(bh[2 * nf2][0]), "=r"(bh[2 * nf2][1]),
                      "=r"(bh[2 * nf2 + 1][0]), "=r"(bh[2 * nf2 + 1][1]) : "r"(adh));
                asm volatile("ldmatrix.sync.aligned.m8n8.x4.shared.b16 {%0,%1,%2,%3}, [%4];"
                    : "=r"(bl[2 * nf2][0]), "=r"(bl[2 * nf2][1]),
                      "=r"(bl[2 * nf2 + 1][0]), "=r"(bl[2 * nf2 + 1][1]) : "r"(adl));
            }
            #pragma unroll
            for (int mf = 0; mf < 2; mf++)
                #pragma unroll
                for (int nf = 0; nf < NF; nf++) {
                    asm volatile(
                        "mma.sync.aligned.m16n8k16.row.col.f32.bf16.bf16.f32 "
                        "{%0,%1,%2,%3}, {%4,%5,%6,%7}, {%8,%9}, {%0,%1,%2,%3};"
                        : "+f"(acc[mf][nf][0]), "+f"(acc[mf][nf][1]),
                          "+f"(acc[mf][nf][2]), "+f"(acc[mf][nf][3])
                        : "r"(ah[mf][0]), "r"(ah[mf][1]), "r"(ah[mf][2]), "r"(ah[mf][3]),
                          "r"(bh[nf][0]), "r"(bh[nf][1]));
                    asm volatile(
                        "mma.sync.aligned.m16n8k16.row.col.f32.bf16.bf16.f32 "
                        "{%0,%1,%2,%3}, {%4,%5,%6,%7}, {%8,%9}, {%0,%1,%2,%3};"
                        : "+f"(acc[mf][nf][0]), "+f"(acc[mf][nf][1]),
                          "+f"(acc[mf][nf][2]), "+f"(acc[mf][nf][3])
                        : "r"(al[mf][0]), "r"(al[mf][1]), "r"(al[mf][2]), "r"(al[mf][3]),
                          "r"(bh[nf][0]), "r"(bh[nf][1]));
                    asm volatile(
                        "mma.sync.aligned.m16n8k16.row.col.f32.bf16.bf16.f32 "
                        "{%0,%1,%2,%3}, {%4,%5,%6,%7}, {%8,%9}, {%0,%1,%2,%3};"
                        : "+f"(acc[mf][nf][0]), "+f"(acc[mf][nf][1]),
                          "+f"(acc[mf][nf][2]), "+f"(acc[mf][nf][3])
                        : "r"(ah[mf][0]), "r"(ah[mf][1]), "r"(ah[mf][2]), "r"(ah[mf][3]),
                          "r"(bl[nf][0]), "r"(bl[nf][1]));
                }
        }
        __syncthreads();
    }

    #pragma unroll
    for (int mf = 0; mf < 2; mf++) {
        int r1 = m0 + wm * 32 + mf * 16 + (lane >> 2);
        int r2 = r1 + 8;
        #pragma unroll
        for (int nf = 0; nf < NF; nf++) {
            int col = wn * (NF * 8) + nf * 8 + (lane & 3) * 2;
            float bx = __ldg(bias + col), by = __ldg(bias + col + 1);
            if (r1 < M) {
                float2 v = make_float2(acc[mf][nf][0] + bx, acc[mf][nf][1] + by);
                *(float2*)(Out + (size_t)r1 * N_ + col) = v;
            }
            if (r2 < M) {
                float2 v = make_float2(acc[mf][nf][2] + bx, acc[mf][nf][3] + by);
                *(float2*)(Out + (size_t)r2 * N_ + col) = v;
            }
        }
    }
}

// ---------------------------------------------------------------------------
// Split helpers
// ---------------------------------------------------------------------------
__device__ __forceinline__ __nv_bfloat162 bhi2(float x, float y) {
    __nv_bfloat162 p;
    p.x = __float2bfloat16(x);
    p.y = __float2bfloat16(y);
    return p;
}
__device__ __forceinline__ __nv_bfloat162 blo2(float x, float y, __nv_bfloat162 h) {
    __nv_bfloat162 p;
    p.x = __float2bfloat16(x - __bfloat162float(h.x));
    p.y = __float2bfloat16(y - __bfloat162float(h.y));
    return p;
}

// x [M,256] f32 -> acat [M,512] = [hi|lo]
__global__ void asplit2(const float* __restrict__ src, __nv_bfloat16* __restrict__ acat, int n4) {
    int i = blockIdx.x * blockDim.x + threadIdx.x;
    if (i >= n4) return;
    int r = i >> 6, c = i & 63;
    float4 v = ((const float4*)src)[i];
    __nv_bfloat162 h0 = bhi2(v.x, v.y), h1 = bhi2(v.z, v.w);
    __nv_bfloat162 l0 = blo2(v.x, v.y, h0), l1 = blo2(v.z, v.w, h1);
    __nv_bfloat162* row = (__nv_bfloat162*)(acat + (size_t)r * 512);
    row[2 * c]           = h0;
    row[2 * c + 1]       = h1;
    row[128 + 2 * c]     = l0;
    row[128 + 2 * c + 1] = l1;
}

// All weights -> [N,2K]=[hi|lo] transposed, one kernel
__global__ void wsplit_all(const float* __restrict__ w1, const float* __restrict__ wm,
                           const float* __restrict__ w2,
                           __nv_bfloat16* __restrict__ w1c, __nv_bfloat16* __restrict__ wmc,
                           __nv_bfloat16* __restrict__ w2c) {
    int i = blockIdx.x * blockDim.x + threadIdx.x;
    float f;
    __nv_bfloat16* dhi;
    int K;
    if (i < DIN * HH) {                       // w1 [256,128] -> w1c [128,512]
        int k = i / HH, n = i % HH;
        f = w1[i];
        dhi = w1c + (size_t)n * 2 * DIN + k;
        K = DIN;
    } else if (i < DIN * HH + 2 * HH * HH) {  // wm [2,128,128] -> wmc [2][128,256]
        int j = i - DIN * HH;
        int l = j >> 14; j &= 16383;
        int k = j / HH, n = j % HH;
        f = wm[(size_t)l * HH * HH + j];
        dhi = wmc + (size_t)l * HH * 2 * HH + (size_t)n * 2 * HH + k;
        K = HH;
    } else if (i < DIN * HH + 2 * HH * HH + HH * CC) {  // w2 [128,64] -> w2c [64,256]
        int j = i - DIN * HH - 2 * HH * HH;
        int k = j / CC, n = j % CC;
        f = w2[j];
        dhi = w2c + (size_t)n * 2 * HH + k;
        K = HH;
    } else return;
    __nv_bfloat16 h = __float2bfloat16(f);
    dhi[0] = h;
    dhi[K] = __float2bfloat16(f - __bfloat162float(h));
}

// ---------------------------------------------------------------------------
// CSR construction (cnt self-zeroing in scan keeps replays deterministic)
// ---------------------------------------------------------------------------
__global__ void hist_kernel(const int* __restrict__ row, int* __restrict__ cnt, int E) {
    int i = blockIdx.x * blockDim.x + threadIdx.x;
    if (i < E) atomicAdd(&cnt[row[i]], 1);
}
__global__ void scan_kernel(int* __restrict__ cnt, int* __restrict__ rowptr,
                            int* __restrict__ cursor) {
    __shared__ int wsum[32];
    __shared__ int carry_s;
    const int tid = threadIdx.x;
    const int lane = tid & 31;
    const int wid = tid >> 5;
    if (tid == 0) { carry_s = 0; rowptr[0] = 0; }
    __syncthreads();
    for (int base = 0; base < NN; base += 1024) {
        int i = base + tid;
        int v = (i < NN) ? cnt[i] : 0;
        if (i < NN) cnt[i] = 0;       // restore invariant for next replay
        int incl = v;
        #pragma unroll
        for (int o = 1; o < 32; o <<= 1) {
            int t = __shfl_up_sync(0xFFFFFFFFu, incl, o);
            if (lane >= o) incl += t;
        }
        if (lane == 31) wsum[wid] = incl;
        __syncthreads();
        if (wid == 0) {
            int w = wsum[lane];
            #pragma unroll
            for (int o = 1; o < 32; o <<= 1) {
                int t = __shfl_up_sync(0xFFFFFFFFu, w, o);
                if (lane >= o) w += t;
            }
            wsum[lane] = w;
        }
        __syncthreads();
        int offset = (wid > 0) ? wsum[wid - 1] : 0;
        int total = wsum[31];
        int carry = carry_s;
        incl += offset;
        if (i < NN) {
            rowptr[i + 1] = carry + incl;
            cursor[i]     = carry + incl - v;
        }
        __syncthreads();
        if (tid == 0) carry_s = carry + total;
        __syncthreads();
    }
}
__global__ void scatter_kernel(const int* __restrict__ row, const int* __restrict__ col,
                               const float* __restrict__ val, int* __restrict__ cursor,
                               int2* __restrict__ cpack, int E) {
    int i = blockIdx.x * blockDim.x + threadIdx.x;
    if (i >= E) return;
    int pos = atomicAdd(&cursor[row[i]], 1);
    cpack[pos] = make_int2(col[i], __float_as_int(val[i]));
}

// ---------------------------------------------------------------------------
// CSR SPMM (1 warp/row), packed edges, fused epilogue + bf16 [hi|lo] split.
// MODE 0: h = relu(acc); split -> acat[.,256]
// MODE 1: h += relu(acc)*dt; split -> acat[.,256]
// MODE 2: dst = acc (D=64)
// ---------------------------------------------------------------------------
template<int D, int MODE>
__global__ void spmm_csr(const int* __restrict__ rowptr, const int2* __restrict__ cpack,
                         const float* __restrict__ mat, float* __restrict__ dst,
                         const float* __restrict__ ts, __nv_bfloat16* __restrict__ acat) {
    int r = blockIdx.x * (blockDim.x >> 5) + (threadIdx.x >> 5);
    if (r >= NN) return;
    int lane = threadIdx.x & 31;
    int s = __ldg(&rowptr[r]);
    int e = __ldg(&rowptr[r + 1]);

    if (D == 128) {
        float4 acc = make_float4(0.f, 0.f, 0.f, 0.f);
        for (int i = s; i < e; i++) {
            int2 ev = __ldg(&cpack[i]);
            float v = __int_as_float(ev.y);
            float4 m = __ldg((const float4*)(mat + (size_t)ev.x * 128) + lane);
            acc.x = fmaf(v, m.x, acc.x);
            acc.y = fmaf(v, m.y, acc.y);
            acc.z = fmaf(v, m.z, acc.z);
            acc.w = fmaf(v, m.w, acc.w);
        }
        float4* o = (float4*)(dst + (size_t)r * 128) + lane;
        float4 hv;
        if (MODE == 0) {
            hv.x = fmaxf(acc.x, 0.f); hv.y = fmaxf(acc.y, 0.f);
            hv.z = fmaxf(acc.z, 0.f); hv.w = fmaxf(acc.w, 0.f);
        } else {
            float dt = *ts;
            hv = *o;
            hv.x = fmaf(fmaxf(acc.x, 0.f), dt, hv.x);
            hv.y = fmaf(fmaxf(acc.y, 0.f), dt, hv.y);
            hv.z = fmaf(fmaxf(acc.z, 0.f), dt, hv.z);
            hv.w = fmaf(fmaxf(acc.w, 0.f), dt, hv.w);
        }
        *o = hv;
        __nv_bfloat162 h0 = bhi2(hv.x, hv.y), h1 = bhi2(hv.z, hv.w);
        __nv_bfloat162 l0 = blo2(hv.x, hv.y, h0), l1 = blo2(hv.z, hv.w, h1);
        __nv_bfloat162* row = (__nv_bfloat162*)(acat + (size_t)r * 256);
        row[2 * lane]          = h0;
        row[2 * lane + 1]      = h1;
        row[64 + 2 * lane]     = l0;
        row[64 + 2 * lane + 1] = l1;
    } else {
        float2 acc = make_float2(0.f, 0.f);
        for (int i = s; i < e; i++) {
            int2 ev = __ldg(&cpack[i]);
            float v = __int_as_float(ev.y);
            float2 m = __ldg((const float2*)(mat + (size_t)ev.x * 64) + lane);
            acc.x = fmaf(v, m.x, acc.x);
            acc.y = fmaf(v, m.y, acc.y);
        }
        *((float2*)(dst + (size_t)r * 64) + lane) = acc;
    }
}

// ---------------------------------------------------------------------------
// Launch sequence
// ---------------------------------------------------------------------------
extern "C" void kernel_launch(void* const* d_in, const int* in_sizes, int n_in,
                              void* d_out, int out_size) {
    const float* x    = (const float*)d_in[0];
    const int*   erow = (const int*)  d_in[1];
    const int*   ecol = (const int*)  d_in[2];
    const float* eval = (const float*)d_in[3];
    const float* w1   = (const float*)d_in[4];
    const float* b1   = (const float*)d_in[5];
    const float* wm   = (const float*)d_in[6];
    const float* bm   = (const float*)d_in[7];
    const float* w2   = (const float*)d_in[8];
    const float* b2   = (const float*)d_in[9];
    const float* ts   = (const float*)d_in[10];
    float* out = (float*)d_out;

    float *y, *h;
    int *cnt, *rowptr, *cursor;
    int2* cpack;
    __nv_bfloat16 *acat, *w1c, *wmc, *w2c;
    cudaGetSymbolAddress((void**)&y,      g_y);
    cudaGetSymbolAddress((void**)&h,      g_h);
    cudaGetSymbolAddress((void**)&cnt,    g_cnt);
    cudaGetSymbolAddress((void**)&rowptr, g_rowptr);
    cudaGetSymbolAddress((void**)&cursor, g_cursor);
    cudaGetSymbolAddress((void**)&cpack,  g_cpack);
    cudaGetSymbolAddress((void**)&acat,   g_acat);
    cudaGetSymbolAddress((void**)&w1c,    g_w1c);
    cudaGetSymbolAddress((void**)&wmc,    g_wmc);
    cudaGetSymbolAddress((void**)&w2c,    g_w2c);

    // Dynamic smem: B resident + 4 A tiles of 16KB
    const int SM1 = 128 * (4 * DIN) + 4 * 128 * 128;  // 196608
    const int SM2 = 128 * (4 * HH)  + 4 * 128 * 128;  // 131072
    const int SM4 = 64  * (4 * HH)  + 4 * 128 * 128;  // 98304
    cudaFuncSetAttribute((const void*)&gemm_mma<128, DIN>,
                         cudaFuncAttributeMaxDynamicSharedMemorySize, SM1);
    cudaFuncSetAttribute((const void*)&gemm_mma<128, HH>,
                         cudaFuncAttributeMaxDynamicSharedMemorySize, SM2);
    cudaFuncSetAttribute((const void*)&gemm_mma<64, HH>,
                         cudaFuncAttributeMaxDynamicSharedMemorySize, SM4);
    cudaGetLastError();

    const int gemm_blocks = (NN + 127) / 128;  // 313
    const int spmm_blocks = (NN + 7) / 8;
    const int e_blocks = (EE + 255) / 256;
    const int w_total = DIN * HH + 2 * HH * HH + HH * CC;

    // Build CSR (cnt assumed 0 at entry; scan re-zeroes it)
    hist_kernel<<<e_blocks, 256>>>(erow, cnt, EE);
    scan_kernel<<<1, 1024>>>(cnt, rowptr, cursor);
    scatter_kernel<<<e_blocks, 256>>>(erow, ecol, eval, cursor, cpack, EE);

    // Split weights
    wsplit_all<<<(w_total + 255) / 256, 256>>>(w1, wm, w2, w1c, wmc, w2c);

    // Stage 1: h = relu(A @ (x W1 + b1))
    asplit2<<<(NN * DIN / 4 + 255) / 256, 256>>>(x, acat, NN * DIN / 4);
    gemm_mma<128, DIN><<<gemm_blocks, 256, SM1>>>(acat, w1c, b1, y, NN);
    spmm_csr<128, 0><<<spmm_blocks, 256>>>(rowptr, cpack, y, h, ts, acat);

    // Stage 2,3: h += relu(A @ (h Wm + bm)) * dt
    for (int i = 0; i < 2; i++) {
        gemm_mma<128, HH><<<gemm_blocks, 256, SM2>>>(
            acat, wmc + (size_t)i * HH * 2 * HH, bm + (size_t)i * HH, y, NN);
        spmm_csr<128, 1><<<spmm_blocks, 256>>>(rowptr, cpack, y, h, ts, acat);
    }

    // Stage 4: out = A @ (h W2 + b2)
    gemm_mma<64, HH><<<gemm_blocks, 256, SM4>>>(acat, w2c, b2, y, NN);
    spmm_csr<64, 2><<<spmm_blocks, 256>>>(rowptr, cpack, y, out, ts, nullptr);
}

// round 6
// speedup vs baseline: 4.1817x; 1.1481x over previous
#include <cuda_runtime.h>
#include <cuda_bf16.h>
#include <cstdint>

#define NN 40000
#define EE 640000
#define DIN 256
#define HH 128
#define CC 64

// ---------------------------------------------------------------------------
// Scratch (device globals — allocation forbidden in kernel_launch)
// ---------------------------------------------------------------------------
__device__ float g_y[NN * HH];
__device__ float g_h[NN * HH];
__device__ __nv_bfloat16 g_acat[(NN + 128) * 2 * DIN];  // A [M,2K]=[hi|lo], padded
__device__ __nv_bfloat16 g_w1c[HH * 2 * DIN];
__device__ __nv_bfloat16 g_wmc[2 * HH * 2 * HH];
__device__ __nv_bfloat16 g_w2c[CC * 2 * HH];
__device__ int  g_cnt[NN];
__device__ int  g_rowptr[NN + 1];
__device__ int  g_cursor[NN];
__device__ int2 g_cpack[EE];

// Side stream + events, created once in static init (BEFORE any capture).
static cudaStream_t g_side = nullptr;
static cudaEvent_t  g_ev0 = nullptr, g_ev1 = nullptr;
static struct _SideInit {
    _SideInit() {
        if (cudaStreamCreateWithFlags(&g_side, cudaStreamNonBlocking) != cudaSuccess) g_side = nullptr;
        if (cudaEventCreateWithFlags(&g_ev0, cudaEventDisableTiming) != cudaSuccess) g_ev0 = nullptr;
        if (cudaEventCreateWithFlags(&g_ev1, cudaEventDisableTiming) != cudaSuccess) g_ev1 = nullptr;
    }
} _side_init;

__device__ __forceinline__ uint32_t smem_u32(const void* p) {
    uint32_t a;
    asm("{ .reg .u64 t; cvta.to.shared.u64 t, %1; cvt.u32.u64 %0, t; }" : "=r"(a) : "l"(p));
    return a;
}
__device__ __forceinline__ void cp16(uint32_t dst, const void* src) {
    asm volatile("cp.async.cg.shared.global [%0], [%1], 16;" :: "r"(dst), "l"(src));
}
#define CP_COMMIT() asm volatile("cp.async.commit_group;" ::: "memory")
#define CP_WAIT1()  asm volatile("cp.async.wait_group 1;" ::: "memory")

// ---------------------------------------------------------------------------
// bf16x3 GEMM via mma.sync.m16n8k16 (unchanged from R5 — verified working).
// ---------------------------------------------------------------------------
template<int N_, int K>
__global__ __launch_bounds__(256)
void gemm_mma(const __nv_bfloat16* __restrict__ A2,
              const __nv_bfloat16* __restrict__ BT2,
              const float* __restrict__ bias,
              float* __restrict__ Out, int M) {
    constexpr int NF = N_ / 16;
    constexpr int NITER = K / 64;
    constexpr int BROW = 4 * K;
    constexpr int ABUF = 128 * 128;

    extern __shared__ uint8_t smem[];
    uint8_t* sB = smem;
    uint8_t* sA = smem + N_ * BROW;
    const uint32_t sBu = smem_u32(sB);
    const uint32_t sAu = smem_u32(sA);

    const int tid = threadIdx.x;
    const int wid = tid >> 5;
    const int lane = tid & 31;
    const int wm = wid >> 1;
    const int wn = wid & 1;
    const int m0 = blockIdx.x * 128;

    float acc[2][NF][4];
    #pragma unroll
    for (int i = 0; i < 2; i++)
        #pragma unroll
        for (int j = 0; j < NF; j++)
            #pragma unroll
            for (int q = 0; q < 4; q++) acc[i][j][q] = 0.f;

    for (int idx = tid; idx < N_ * (2 * K) / 8; idx += 256) {
        int r = idx / ((2 * K) / 8);
        int kz = (idx % ((2 * K) / 8)) * 8;
        uint32_t dst = sBu + r * BROW + ((kz >> 6) << 7) + ((((kz >> 3) & 7) ^ (r & 7)) << 4);
        cp16(dst, BT2 + (size_t)r * 2 * K + kz);
    }
    auto stageA = [&](int it, int buf) {
        #pragma unroll
        for (int s = 0; s < 8; s++) {
            int idx = s * 256 + tid;
            int hilo = idx >> 10;
            int rem = idx & 1023;
            int r = rem >> 3, c = rem & 7;
            uint32_t dst = sAu + (uint32_t)(buf * 2 + hilo) * ABUF + r * 128 + ((c ^ (r & 7)) << 4);
            cp16(dst, A2 + (size_t)(m0 + r) * 2 * K + hilo * K + it * 64 + c * 8);
        }
    };
    stageA(0, 0);
    CP_COMMIT();

    for (int it = 0; it < NITER; it++) {
        const int buf = it & 1;
        if (it + 1 < NITER) stageA(it + 1, buf ^ 1);
        CP_COMMIT();
        CP_WAIT1();
        __syncthreads();

        const uint32_t aHi = sAu + (uint32_t)(buf * 2) * ABUF;
        const uint32_t aLo = aHi + ABUF;
        #pragma unroll
        for (int ks = 0; ks < 4; ks++) {
            const int kk = ks * 16;
            uint32_t ah[2][4], al[2][4];
            #pragma unroll
            for (int mf = 0; mf < 2; mf++) {
                int r = wm * 32 + mf * 16 + (lane & 15);
                int kz = kk + (lane >> 4) * 8;
                uint32_t off = r * 128 + ((((kz >> 3) ^ (r & 7)) & 7) << 4);
                asm volatile("ldmatrix.sync.aligned.m8n8.x4.shared.b16 {%0,%1,%2,%3}, [%4];"
                    : "=r"(ah[mf][0]), "=r"(ah[mf][1]), "=r"(ah[mf][2]), "=r"(ah[mf][3])
                    : "r"(aHi + off));
                asm volatile("ldmatrix.sync.aligned.m8n8.x4.shared.b16 {%0,%1,%2,%3}, [%4];"
                    : "=r"(al[mf][0]), "=r"(al[mf][1]), "=r"(al[mf][2]), "=r"(al[mf][3])
                    : "r"(aLo + off));
            }
            uint32_t bh[NF][2], bl[NF][2];
            #pragma unroll
            for (int nf2 = 0; nf2 < NF / 2; nf2++) {
                int r = wn * (NF * 8) + nf2 * 16 + (lane & 7) + ((lane >> 4) << 3);
                int kzh = it * 64 + kk + ((lane >> 3) & 1) * 8;
                int kzl = kzh + K;
                uint32_t adh = sBu + r * BROW + ((kzh >> 6) << 7) + ((((kzh >> 3) & 7) ^ (r & 7)) << 4);
                uint32_t adl = sBu + r * BROW + ((kzl >> 6) << 7) + ((((kzl >> 3) & 7) ^ (r & 7)) << 4);
                asm volatile("ldmatrix.sync.aligned.m8n8.x4.shared.b16 {%0,%1,%2,%3}, [%4];"
                    : "=r"(bh[2 * nf2][0]), "=r"(bh[2 * nf2][1]),
                      "=r"(bh[2 * nf2 + 1][0]), "=r"(bh[2 * nf2 + 1][1]) : "r"(adh));
                asm volatile("ldmatrix.sync.aligned.m8n8.x4.shared.b16 {%0,%1,%2,%3}, [%4];"
                    : "=r"(bl[2 * nf2][0]), "=r"(bl[2 * nf2][1]),
                      "=r"(bl[2 * nf2 + 1][0]), "=r"(bl[2 * nf2 + 1][1]) : "r"(adl));
            }
            #pragma unroll
            for (int mf = 0; mf < 2; mf++)
                #pragma unroll
                for (int nf = 0; nf < NF; nf++) {
                    asm volatile(
                        "mma.sync.aligned.m16n8k16.row.col.f32.bf16.bf16.f32 "
                        "{%0,%1,%2,%3}, {%4,%5,%6,%7}, {%8,%9}, {%0,%1,%2,%3};"
                        : "+f"(acc[mf][nf][0]), "+f"(acc[mf][nf][1]),
                          "+f"(acc[mf][nf][2]), "+f"(acc[mf][nf][3])
                        : "r"(ah[mf][0]), "r"(ah[mf][1]), "r"(ah[mf][2]), "r"(ah[mf][3]),
                          "r"(bh[nf][0]), "r"(bh[nf][1]));
                    asm volatile(
                        "mma.sync.aligned.m16n8k16.row.col.f32.bf16.bf16.f32 "
                        "{%0,%1,%2,%3}, {%4,%5,%6,%7}, {%8,%9}, {%0,%1,%2,%3};"
                        : "+f"(acc[mf][nf][0]), "+f"(acc[mf][nf][1]),
                          "+f"(acc[mf][nf][2]), "+f"(acc[mf][nf][3])
                        : "r"(al[mf][0]), "r"(al[mf][1]), "r"(al[mf][2]), "r"(al[mf][3]),
                          "r"(bh[nf][0]), "r"(bh[nf][1]));
                    asm volatile(
                        "mma.sync.aligned.m16n8k16.row.col.f32.bf16.bf16.f32 "
                        "{%0,%1,%2,%3}, {%4,%5,%6,%7}, {%8,%9}, {%0,%1,%2,%3};"
                        : "+f"(acc[mf][nf][0]), "+f"(acc[mf][nf][1]),
                          "+f"(acc[mf][nf][2]), "+f"(acc[mf][nf][3])
                        : "r"(ah[mf][0]), "r"(ah[mf][1]), "r"(ah[mf][2]), "r"(ah[mf][3]),
                          "r"(bl[nf][0]), "r"(bl[nf][1]));
                }
        }
        __syncthreads();
    }

    #pragma unroll
    for (int mf = 0; mf < 2; mf++) {
        int r1 = m0 + wm * 32 + mf * 16 + (lane >> 2);
        int r2 = r1 + 8;
        #pragma unroll
        for (int nf = 0; nf < NF; nf++) {
            int col = wn * (NF * 8) + nf * 8 + (lane & 3) * 2;
            float bx = __ldg(bias + col), by = __ldg(bias + col + 1);
            if (r1 < M) {
                float2 v = make_float2(acc[mf][nf][0] + bx, acc[mf][nf][1] + by);
                *(float2*)(Out + (size_t)r1 * N_ + col) = v;
            }
            if (r2 < M) {
                float2 v = make_float2(acc[mf][nf][2] + bx, acc[mf][nf][3] + by);
                *(float2*)(Out + (size_t)r2 * N_ + col) = v;
            }
        }
    }
}

// ---------------------------------------------------------------------------
// Split helpers
// ---------------------------------------------------------------------------
__device__ __forceinline__ __nv_bfloat162 bhi2(float x, float y) {
    __nv_bfloat162 p;
    p.x = __float2bfloat16(x);
    p.y = __float2bfloat16(y);
    return p;
}
__device__ __forceinline__ __nv_bfloat162 blo2(float x, float y, __nv_bfloat162 h) {
    __nv_bfloat162 p;
    p.x = __float2bfloat16(x - __bfloat162float(h.x));
    p.y = __float2bfloat16(y - __bfloat162float(h.y));
    return p;
}

// Merged prep: x -> acat[hi|lo]  AND  all weights -> [N,2K]=[hi|lo] transposed
__global__ void prep_kernel(const float* __restrict__ x,
                            const float* __restrict__ w1, const float* __restrict__ wm,
                            const float* __restrict__ w2,
                            __nv_bfloat16* __restrict__ acat,
                            __nv_bfloat16* __restrict__ w1c, __nv_bfloat16* __restrict__ wmc,
                            __nv_bfloat16* __restrict__ w2c) {
    const int XN4 = NN * DIN / 4;
    int i = blockIdx.x * blockDim.x + threadIdx.x;
    if (i < XN4) {
        int r = i >> 6, c = i & 63;
        float4 v = ((const float4*)x)[i];
        __nv_bfloat162 h0 = bhi2(v.x, v.y), h1 = bhi2(v.z, v.w);
        __nv_bfloat162 l0 = blo2(v.x, v.y, h0), l1 = blo2(v.z, v.w, h1);
        __nv_bfloat162* row = (__nv_bfloat162*)(acat + (size_t)r * 512);
        row[2 * c]           = h0;
        row[2 * c + 1]       = h1;
        row[128 + 2 * c]     = l0;
        row[128 + 2 * c + 1] = l1;
        return;
    }
    int j = i - XN4;
    float f;
    __nv_bfloat16* dhi;
    int K;
    if (j < DIN * HH) {
        int k = j / HH, n = j % HH;
        f = w1[j];
        dhi = w1c + (size_t)n * 2 * DIN + k;
        K = DIN;
    } else if (j < DIN * HH + 2 * HH * HH) {
        int q = j - DIN * HH;
        int l = q >> 14; q &= 16383;
        int k = q / HH, n = q % HH;
        f = wm[(size_t)l * HH * HH + (q)];
        dhi = wmc + (size_t)l * HH * 2 * HH + (size_t)n * 2 * HH + k;
        K = HH;
    } else if (j < DIN * HH + 2 * HH * HH + HH * CC) {
        int q = j - DIN * HH - 2 * HH * HH;
        int k = q / CC, n = q % CC;
        f = w2[q];
        dhi = w2c + (size_t)n * 2 * HH + k;
        K = HH;
    } else return;
    __nv_bfloat16 h = __float2bfloat16(f);
    dhi[0] = h;
    dhi[K] = __float2bfloat16(f - __bfloat162float(h));
}

// ---------------------------------------------------------------------------
// CSR construction (cnt self-zeroing keeps replays deterministic)
// ---------------------------------------------------------------------------
__global__ void hist_kernel(const int* __restrict__ row, int* __restrict__ cnt, int E) {
    int i = blockIdx.x * blockDim.x + threadIdx.x;
    if (i < E) atomicAdd(&cnt[row[i]], 1);
}
__global__ void scan_kernel(int* __restrict__ cnt, int* __restrict__ rowptr,
                            int* __restrict__ cursor) {
    __shared__ int wsum[32];
    __shared__ int carry_s;
    const int tid = threadIdx.x;
    const int lane = tid & 31;
    const int wid = tid >> 5;
    if (tid == 0) { carry_s = 0; rowptr[0] = 0; }
    __syncthreads();
    for (int base = 0; base < NN; base += 1024) {
        int i = base + tid;
        int v = (i < NN) ? cnt[i] : 0;
        if (i < NN) cnt[i] = 0;
        int incl = v;
        #pragma unroll
        for (int o = 1; o < 32; o <<= 1) {
            int t = __shfl_up_sync(0xFFFFFFFFu, incl, o);
            if (lane >= o) incl += t;
        }
        if (lane == 31) wsum[wid] = incl;
        __syncthreads();
        if (wid == 0) {
            int w = wsum[lane];
            #pragma unroll
            for (int o = 1; o < 32; o <<= 1) {
                int t = __shfl_up_sync(0xFFFFFFFFu, w, o);
                if (lane >= o) w += t;
            }
            wsum[lane] = w;
        }
        __syncthreads();
        int offset = (wid > 0) ? wsum[wid - 1] : 0;
        int total = wsum[31];
        int carry = carry_s;
        incl += offset;
        if (i < NN) {
            rowptr[i + 1] = carry + incl;
            cursor[i]     = carry + incl - v;
        }
        __syncthreads();
        if (tid == 0) carry_s = carry + total;
        __syncthreads();
    }
}
__global__ void scatter_kernel(const int* __restrict__ row, const int* __restrict__ col,
                               const float* __restrict__ val, int* __restrict__ cursor,
                               int2* __restrict__ cpack, int E) {
    int i = blockIdx.x * blockDim.x + threadIdx.x;
    if (i >= E) return;
    int pos = atomicAdd(&cursor[row[i]], 1);
    cpack[pos] = make_int2(col[i], __float_as_int(val[i]));
}

// ---------------------------------------------------------------------------
// CSR SPMM (1 warp/row), 4-deep software-pipelined gather, fused epilogue.
// ---------------------------------------------------------------------------
template<int D, int MODE>
__global__ void spmm_csr(const int* __restrict__ rowptr, const int2* __restrict__ cpack,
                         const float* __restrict__ mat, float* __restrict__ dst,
                         const float* __restrict__ ts, __nv_bfloat16* __restrict__ acat) {
    int r = blockIdx.x * (blockDim.x >> 5) + (threadIdx.x >> 5);
    if (r >= NN) return;
    int lane = threadIdx.x & 31;
    int s = __ldg(&rowptr[r]);
    int e = __ldg(&rowptr[r + 1]);

    if (D == 128) {
        float4 acc = make_float4(0.f, 0.f, 0.f, 0.f);
        int i = s;
        for (; i + 4 <= e; i += 4) {
            int2 p0 = __ldg(&cpack[i]);
            int2 p1 = __ldg(&cpack[i + 1]);
            int2 p2 = __ldg(&cpack[i + 2]);
            int2 p3 = __ldg(&cpack[i + 3]);
            float4 m0 = __ldg((const float4*)(mat + (size_t)p0.x * 128) + lane);
            float4 m1 = __ldg((const float4*)(mat + (size_t)p1.x * 128) + lane);
            float4 m2 = __ldg((const float4*)(mat + (size_t)p2.x * 128) + lane);
            float4 m3 = __ldg((const float4*)(mat + (size_t)p3.x * 128) + lane);
            float v0 = __int_as_float(p0.y), v1 = __int_as_float(p1.y);
            float v2 = __int_as_float(p2.y), v3 = __int_as_float(p3.y);
            acc.x = fmaf(v0, m0.x, acc.x); acc.y = fmaf(v0, m0.y, acc.y);
            acc.z = fmaf(v0, m0.z, acc.z); acc.w = fmaf(v0, m0.w, acc.w);
            acc.x = fmaf(v1, m1.x, acc.x); acc.y = fmaf(v1, m1.y, acc.y);
            acc.z = fmaf(v1, m1.z, acc.z); acc.w = fmaf(v1, m1.w, acc.w);
            acc.x = fmaf(v2, m2.x, acc.x); acc.y = fmaf(v2, m2.y, acc.y);
            acc.z = fmaf(v2, m2.z, acc.z); acc.w = fmaf(v2, m2.w, acc.w);
            acc.x = fmaf(v3, m3.x, acc.x); acc.y = fmaf(v3, m3.y, acc.y);
            acc.z = fmaf(v3, m3.z, acc.z); acc.w = fmaf(v3, m3.w, acc.w);
        }
        for (; i < e; i++) {
            int2 p = __ldg(&cpack[i]);
            float v = __int_as_float(p.y);
            float4 m = __ldg((const float4*)(mat + (size_t)p.x * 128) + lane);
            acc.x = fmaf(v, m.x, acc.x); acc.y = fmaf(v, m.y, acc.y);
            acc.z = fmaf(v, m.z, acc.z); acc.w = fmaf(v, m.w, acc.w);
        }
        float4* o = (float4*)(dst + (size_t)r * 128) + lane;
        float4 hv;
        if (MODE == 0) {
            hv.x = fmaxf(acc.x, 0.f); hv.y = fmaxf(acc.y, 0.f);
            hv.z = fmaxf(acc.z, 0.f); hv.w = fmaxf(acc.w, 0.f);
        } else {
            float dt = *ts;
            hv = *o;
            hv.x = fmaf(fmaxf(acc.x, 0.f), dt, hv.x);
            hv.y = fmaf(fmaxf(acc.y, 0.f), dt, hv.y);
            hv.z = fmaf(fmaxf(acc.z, 0.f), dt, hv.z);
            hv.w = fmaf(fmaxf(acc.w, 0.f), dt, hv.w);
        }
        *o = hv;
        __nv_bfloat162 h0 = bhi2(hv.x, hv.y), h1 = bhi2(hv.z, hv.w);
        __nv_bfloat162 l0 = blo2(hv.x, hv.y, h0), l1 = blo2(hv.z, hv.w, h1);
        __nv_bfloat162* row = (__nv_bfloat162*)(acat + (size_t)r * 256);
        row[2 * lane]          = h0;
        row[2 * lane + 1]      = h1;
        row[64 + 2 * lane]     = l0;
        row[64 + 2 * lane + 1] = l1;
    } else {
        float2 acc = make_float2(0.f, 0.f);
        int i = s;
        for (; i + 4 <= e; i += 4) {
            int2 p0 = __ldg(&cpack[i]);
            int2 p1 = __ldg(&cpack[i + 1]);
            int2 p2 = __ldg(&cpack[i + 2]);
            int2 p3 = __ldg(&cpack[i + 3]);
            float2 m0 = __ldg((const float2*)(mat + (size_t)p0.x * 64) + lane);
            float2 m1 = __ldg((const float2*)(mat + (size_t)p1.x * 64) + lane);
            float2 m2 = __ldg((const float2*)(mat + (size_t)p2.x * 64) + lane);
            float2 m3 = __ldg((const float2*)(mat + (size_t)p3.x * 64) + lane);
            acc.x = fmaf(__int_as_float(p0.y), m0.x, acc.x);
            acc.y = fmaf(__int_as_float(p0.y), m0.y, acc.y);
            acc.x = fmaf(__int_as_float(p1.y), m1.x, acc.x);
            acc.y = fmaf(__int_as_float(p1.y), m1.y, acc.y);
            acc.x = fmaf(__int_as_float(p2.y), m2.x, acc.x);
            acc.y = fmaf(__int_as_float(p2.y), m2.y, acc.y);
            acc.x = fmaf(__int_as_float(p3.y), m3.x, acc.x);
            acc.y = fmaf(__int_as_float(p3.y), m3.y, acc.y);
        }
        for (; i < e; i++) {
            int2 p = __ldg(&cpack[i]);
            float v = __int_as_float(p.y);
            float2 m = __ldg((const float2*)(mat + (size_t)p.x * 64) + lane);
            acc.x = fmaf(v, m.x, acc.x);
            acc.y = fmaf(v, m.y, acc.y);
        }
        *((float2*)(dst + (size_t)r * 64) + lane) = acc;
    }
}

// ---------------------------------------------------------------------------
// Launch sequence (CSR build forked onto side stream, joined before spmm-1)
// ---------------------------------------------------------------------------
extern "C" void kernel_launch(void* const* d_in, const int* in_sizes, int n_in,
                              void* d_out, int out_size) {
    const float* x    = (const float*)d_in[0];
    const int*   erow = (const int*)  d_in[1];
    const int*   ecol = (const int*)  d_in[2];
    const float* eval = (const float*)d_in[3];
    const float* w1   = (const float*)d_in[4];
    const float* b1   = (const float*)d_in[5];
    const float* wm   = (const float*)d_in[6];
    const float* bm   = (const float*)d_in[7];
    const float* w2   = (const float*)d_in[8];
    const float* b2   = (const float*)d_in[9];
    const float* ts   = (const float*)d_in[10];
    float* out = (float*)d_out;

    float *y, *h;
    int *cnt, *rowptr, *cursor;
    int2* cpack;
    __nv_bfloat16 *acat, *w1c, *wmc, *w2c;
    cudaGetSymbolAddress((void**)&y,      g_y);
    cudaGetSymbolAddress((void**)&h,      g_h);
    cudaGetSymbolAddress((void**)&cnt,    g_cnt);
    cudaGetSymbolAddress((void**)&rowptr, g_rowptr);
    cudaGetSymbolAddress((void**)&cursor, g_cursor);
    cudaGetSymbolAddress((void**)&cpack,  g_cpack);
    cudaGetSymbolAddress((void**)&acat,   g_acat);
    cudaGetSymbolAddress((void**)&w1c,    g_w1c);
    cudaGetSymbolAddress((void**)&wmc,    g_wmc);
    cudaGetSymbolAddress((void**)&w2c,    g_w2c);

    const int SM1 = 128 * (4 * DIN) + 4 * 128 * 128;
    const int SM2 = 128 * (4 * HH)  + 4 * 128 * 128;
    const int SM4 = 64  * (4 * HH)  + 4 * 128 * 128;
    cudaFuncSetAttribute((const void*)&gemm_mma<128, DIN>,
                         cudaFuncAttributeMaxDynamicSharedMemorySize, SM1);
    cudaFuncSetAttribute((const void*)&gemm_mma<128, HH>,
                         cudaFuncAttributeMaxDynamicSharedMemorySize, SM2);
    cudaFuncSetAttribute((const void*)&gemm_mma<64, HH>,
                         cudaFuncAttributeMaxDynamicSharedMemorySize, SM4);
    cudaGetLastError();

    const int gemm_blocks = (NN + 127) / 128;
    const int spmm_blocks = (NN + 7) / 8;
    const int e_blocks = (EE + 255) / 256;
    const int prep_total = NN * DIN / 4 + DIN * HH + 2 * HH * HH + HH * CC;

    const bool fork = (g_side != nullptr) && (g_ev0 != nullptr) && (g_ev1 != nullptr);

    if (fork) {
        // Fork: CSR build on side stream, concurrent with prep + gemm1
        cudaEventRecord(g_ev0, 0);
        cudaStreamWaitEvent(g_side, g_ev0, 0);
        hist_kernel<<<e_blocks, 256, 0, g_side>>>(erow, cnt, EE);
        scan_kernel<<<1, 1024, 0, g_side>>>(cnt, rowptr, cursor);
        scatter_kernel<<<e_blocks, 256, 0, g_side>>>(erow, ecol, eval, cursor, cpack, EE);
        cudaEventRecord(g_ev1, g_side);
    }

    // Main stream: split inputs/weights, then stage-1 GEMM
    prep_kernel<<<(prep_total + 255) / 256, 256>>>(x, w1, wm, w2, acat, w1c, wmc, w2c);
    gemm_mma<128, DIN><<<gemm_blocks, 256, SM1>>>(acat, w1c, b1, y, NN);

    if (fork) {
        cudaStreamWaitEvent(0, g_ev1, 0);   // join CSR branch
    } else {
        hist_kernel<<<e_blocks, 256>>>(erow, cnt, EE);
        scan_kernel<<<1, 1024>>>(cnt, rowptr, cursor);
        scatter_kernel<<<e_blocks, 256>>>(erow, ecol, eval, cursor, cpack, EE);
    }

    // Stage 1: h = relu(A @ (x W1 + b1))
    spmm_csr<128, 0><<<spmm_blocks, 256>>>(rowptr, cpack, y, h, ts, acat);

    // Stage 2,3: h += relu(A @ (h Wm + bm)) * dt
    for (int i = 0; i < 2; i++) {
        gemm_mma<128, HH><<<gemm_blocks, 256, SM2>>>(
            acat, wmc + (size_t)i * HH * 2 * HH, bm + (size_t)i * HH, y, NN);
        spmm_csr<128, 1><<<spmm_blocks, 256>>>(rowptr, cpack, y, h, ts, acat);
    }

    // Stage 4: out = A @ (h W2 + b2)
    gemm_mma<64, HH><<<gemm_blocks, 256, SM4>>>(acat, w2c, b2, y, NN);
    spmm_csr<64, 2><<<spmm_blocks, 256>>>(rowptr, cpack, y, out, ts, nullptr);
}